// round 1
// baseline (speedup 1.0000x reference)
#include <cuda_runtime.h>
#include <math.h>

#define BB_ 512
#define NN_ 4096
#define DD_ 128
#define HH_ 8
#define TPREV_ 2048
#define S1_ 4
#define S2_ 8
#define CHUNK_ 512            // tokens per split CTA (2048/4 and 4096/8)
#define PSTRIDE_ 144          // 8 m + 8 l + 128 acc

// ---------------- device scratch (static; no allocations) ----------------
__device__ float g_q[BB_ * DD_];
__device__ float g_kself[BB_ * DD_];
__device__ float g_vself[BB_ * DD_];
__device__ float g_ht1[BB_ * DD_];
__device__ float g_query[BB_ * DD_];
__device__ float g_part1[BB_ * S1_ * PSTRIDE_];
__device__ float g_part2[BB_ * S2_ * PSTRIDE_];

// ---------------- helpers ----------------
__device__ __forceinline__ float warp_sum(float v) {
    v += __shfl_xor_sync(0xffffffffu, v, 16);
    v += __shfl_xor_sync(0xffffffffu, v, 8);
    v += __shfl_xor_sync(0xffffffffu, v, 4);
    v += __shfl_xor_sync(0xffffffffu, v, 2);
    v += __shfl_xor_sync(0xffffffffu, v, 1);
    return v;
}

// block of 128 threads (4 warps) sum
__device__ __forceinline__ float blk_sum128(float v, float* red, int lane, int warp) {
    v = warp_sum(v);
    __syncthreads();                 // protect red from previous use
    if (lane == 0) red[warp] = v;
    __syncthreads();
    return red[0] + red[1] + red[2] + red[3];
}

// y[r] = sum_j x[j] * Wm[r*128 + j] + bm[r]; 128 threads, warp-per-row.
__device__ __forceinline__ void gemv128(const float* __restrict__ Wm,
                                        const float* __restrict__ bm,
                                        const float* __restrict__ shx,
                                        float* __restrict__ shy,
                                        int lane, int warp) {
    float4 xv = ((const float4*)shx)[lane];
#pragma unroll 4
    for (int r = warp; r < DD_; r += 4) {
        float4 wv = __ldg(((const float4*)(Wm + r * DD_)) + lane);
        float p = fmaf(wv.x, xv.x, fmaf(wv.y, xv.y, fmaf(wv.z, xv.z, wv.w * xv.w)));
        p = warp_sum(p);
        if (lane == 0) shy[r] = p + bm[r];
    }
}

// ---------------- K0: q/k/v projections of ht ----------------
__global__ void qkv_kernel(const float* __restrict__ ht,
                           const float* __restrict__ W,
                           const float* __restrict__ bb) {
    int b = blockIdx.x;
    int tid = threadIdx.x, lane = tid & 31, warp = tid >> 5;
    __shared__ __align__(16) float shx[DD_];
    shx[tid] = ht[b * DD_ + tid];
    __syncthreads();
    float4 xv = ((const float4*)shx)[lane];
#pragma unroll
    for (int m = 0; m < 3; m++) {
        const float* Wm = W + m * DD_ * DD_;
        const float* bm = bb + m * DD_;
        float* out = (m == 0) ? g_q : ((m == 1) ? g_kself : g_vself);
#pragma unroll 4
        for (int r = warp; r < DD_; r += 4) {
            float4 wv = __ldg(((const float4*)(Wm + r * DD_)) + lane);
            float p = fmaf(wv.x, xv.x, fmaf(wv.y, xv.y, fmaf(wv.z, xv.z, wv.w * xv.w)));
            p = warp_sum(p);
            if (lane == 0) out[b * DD_ + r] = p + bm[r];
        }
    }
}

// ---------------- streaming split attention ----------------
template <bool MASKED>
__device__ __forceinline__ void attn_split_body(const float* __restrict__ Kv,
                                                const float* __restrict__ Vv,
                                                const int* __restrict__ mask,
                                                const float* __restrict__ qsrc,
                                                float* __restrict__ part,
                                                int T) {
    const int s = blockIdx.x, b = blockIdx.y;
    const int tid = threadIdx.x, lane = tid & 31, warp = tid >> 5;   // 8 warps

    __shared__ __align__(16) float shq[DD_];
    __shared__ int shmask[CHUNK_];
    if (tid < DD_) shq[tid] = qsrc[b * DD_ + tid];
    if (MASKED) {
#pragma unroll
        for (int i = tid; i < CHUNK_; i += 256)
            shmask[i] = mask[(size_t)b * T + (size_t)s * CHUNK_ + i];
    }
    __syncthreads();

    const float4 qv = ((const float4*)shq)[lane];
    const size_t base4 = ((size_t)b * T + (size_t)s * CHUNK_) * (DD_ / 4);
    const float4* Kb = ((const float4*)Kv) + base4;
    const float4* Vb = ((const float4*)Vv) + base4;

    float m = -INFINITY, l = 0.f;
    float4 acc = make_float4(0.f, 0.f, 0.f, 0.f);

#pragma unroll 4
    for (int t = warp; t < CHUNK_; t += 8) {
        float4 k4 = __ldcs(&Kb[t * 32 + lane]);
        float4 v4 = __ldcs(&Vb[t * 32 + lane]);
        float dt = fmaf(k4.x, qv.x, fmaf(k4.y, qv.y, fmaf(k4.z, qv.z, k4.w * qv.w)));
        dt += __shfl_xor_sync(0xffffffffu, dt, 1);
        dt += __shfl_xor_sync(0xffffffffu, dt, 2);   // head dot (4-lane group)
        float sc = dt * 0.25f;                        // 1/sqrt(16)
        if (MASKED) { if (shmask[t] == 1) sc = -1e9f; }
        float mn = fmaxf(m, sc);
        float scale = __expf(m - mn);                 // exp(-inf)=0 on first iter
        float p = __expf(sc - mn);
        l = fmaf(l, scale, p);
        acc.x = fmaf(acc.x, scale, p * v4.x);
        acc.y = fmaf(acc.y, scale, p * v4.y);
        acc.z = fmaf(acc.z, scale, p * v4.z);
        acc.w = fmaf(acc.w, scale, p * v4.w);
        m = mn;
    }

    // cross-warp merge inside CTA
    __shared__ float sm_m[8][HH_], sm_l[8][HH_];
    __shared__ __align__(16) float sm_acc[8][DD_];
    int head = lane >> 2;
    if ((lane & 3) == 0) { sm_m[warp][head] = m; sm_l[warp][head] = l; }
    ((float4*)sm_acc[warp])[lane] = acc;
    __syncthreads();

    if (tid < DD_) {
        int h = tid >> 4;
        float M = -INFINITY;
#pragma unroll
        for (int w = 0; w < 8; w++) M = fmaxf(M, sm_m[w][h]);
        float L = 0.f, A = 0.f;
#pragma unroll
        for (int w = 0; w < 8; w++) {
            float e = __expf(sm_m[w][h] - M);
            L = fmaf(e, sm_l[w][h], L);
            A = fmaf(e, sm_acc[w][tid], A);
        }
        float* pp = part + ((size_t)b * gridDim.x + s) * PSTRIDE_;
        if ((tid & 15) == 0) { pp[h] = M; pp[8 + h] = L; }
        pp[16 + tid] = A;
    }
}

__global__ void __launch_bounds__(256) attn1_split_k(const float* __restrict__ Kv,
                                                     const float* __restrict__ Vv) {
    attn_split_body<false>(Kv, Vv, nullptr, g_q, g_part1, TPREV_);
}

__global__ void __launch_bounds__(256) attn2_split_k(const float* __restrict__ Kv,
                                                     const float* __restrict__ Vv,
                                                     const int* __restrict__ mask) {
    attn_split_body<true>(Kv, Vv, mask, g_query, g_part2, NN_);
}

// ---------------- K2: merge attn1 + self token, proj W3, residual, LN0, proj W4 -> query
__global__ void reduce1_k(const float* __restrict__ ht0,
                          const float* __restrict__ W,
                          const float* __restrict__ bb,
                          const float* __restrict__ lng,
                          const float* __restrict__ lnb) {
    int b = blockIdx.x, tid = threadIdx.x, lane = tid & 31, warp = tid >> 5;
    int h = tid >> 4;
    __shared__ __align__(16) float shA[DD_], shB[DD_];
    __shared__ __align__(16) float sq[DD_], sk[DD_];
    __shared__ float red[4];

    sq[tid] = g_q[b * DD_ + tid];
    sk[tid] = g_kself[b * DD_ + tid];
    __syncthreads();

    // self-token score for this thread's head
    float qk = 0.f;
#pragma unroll
    for (int j = 0; j < 16; j++) qk = fmaf(sq[h * 16 + j], sk[h * 16 + j], qk);
    float M = qk * 0.25f, L = 1.f, A = g_vself[b * DD_ + tid];

    const float* pp = g_part1 + (size_t)b * S1_ * PSTRIDE_;
#pragma unroll
    for (int s = 0; s < S1_; s++) {
        const float* p = pp + s * PSTRIDE_;
        float ms = p[h], ls = p[8 + h], as = p[16 + tid];
        float Mn = fmaxf(M, ms);
        float e0 = __expf(M - Mn), e1 = __expf(ms - Mn);
        A = A * e0 + as * e1;
        L = L * e0 + ls * e1;
        M = Mn;
    }
    shA[tid] = A / L;
    __syncthreads();

    gemv128(W + 3 * DD_ * DD_, bb + 3 * DD_, shA, shB, lane, warp);
    __syncthreads();

    float v = ht0[b * DD_ + tid] + shB[tid];
    float mean = blk_sum128(v, red, lane, warp) * (1.f / 128.f);
    float dv = v - mean;
    float var = blk_sum128(dv * dv, red, lane, warp) * (1.f / 128.f);
    float ln = dv * rsqrtf(var + 1e-5f) * lng[tid] + lnb[tid];
    g_ht1[b * DD_ + tid] = ln;
    __syncthreads();
    shA[tid] = ln;
    __syncthreads();
    gemv128(W + 4 * DD_ * DD_, bb + 4 * DD_, shA, shB, lane, warp);
    __syncthreads();
    g_query[b * DD_ + tid] = shB[tid];
}

// ---------------- K4: merge attn2, proj W5, residual, LN1, FFN (W7 relu W6), LN2 -> out
__global__ void reduce2_k(const float* __restrict__ W,
                          const float* __restrict__ bb,
                          const float* __restrict__ lng,
                          const float* __restrict__ lnb,
                          float* __restrict__ out) {
    int b = blockIdx.x, tid = threadIdx.x, lane = tid & 31, warp = tid >> 5;
    int h = tid >> 4;
    __shared__ __align__(16) float shA[DD_], shB[DD_];
    __shared__ float red[4];

    const float* pp = g_part2 + (size_t)b * S2_ * PSTRIDE_;
    float M = pp[h], L = pp[8 + h], A = pp[16 + tid];
#pragma unroll
    for (int s = 1; s < S2_; s++) {
        const float* p = pp + s * PSTRIDE_;
        float ms = p[h], ls = p[8 + h], as = p[16 + tid];
        float Mn = fmaxf(M, ms);
        float e0 = __expf(M - Mn), e1 = __expf(ms - Mn);
        A = A * e0 + as * e1;
        L = L * e0 + ls * e1;
        M = Mn;
    }
    shA[tid] = A / L;
    __syncthreads();

    gemv128(W + 5 * DD_ * DD_, bb + 5 * DD_, shA, shB, lane, warp);
    __syncthreads();

    float v = g_ht1[b * DD_ + tid] + shB[tid];
    float mean = blk_sum128(v, red, lane, warp) * (1.f / 128.f);
    float dv = v - mean;
    float var = blk_sum128(dv * dv, red, lane, warp) * (1.f / 128.f);
    float ht2 = dv * rsqrtf(var + 1e-5f) * lng[DD_ + tid] + lnb[DD_ + tid];
    __syncthreads();
    shA[tid] = ht2;
    __syncthreads();

    gemv128(W + 7 * DD_ * DD_, bb + 7 * DD_, shA, shB, lane, warp);   // FFN in
    __syncthreads();
    shB[tid] = fmaxf(shB[tid], 0.f);                                   // relu
    __syncthreads();
    gemv128(W + 6 * DD_ * DD_, bb + 6 * DD_, shB, shA, lane, warp);   // FFN out
    __syncthreads();

    float v2 = ht2 + shA[tid];
    float mean2 = blk_sum128(v2, red, lane, warp) * (1.f / 128.f);
    float dv2 = v2 - mean2;
    float var2 = blk_sum128(dv2 * dv2, red, lane, warp) * (1.f / 128.f);
    out[b * DD_ + tid] = dv2 * rsqrtf(var2 + 1e-5f) * lng[2 * DD_ + tid] + lnb[2 * DD_ + tid];
}

// ---------------- launch ----------------
extern "C" void kernel_launch(void* const* d_in, const int* in_sizes, int n_in,
                              void* d_out, int out_size) {
    const float* ht    = (const float*)d_in[0];
    const float* key   = (const float*)d_in[1];
    const float* value = (const float*)d_in[2];
    const int*   mask  = (const int*)  d_in[3];
    const float* kprev = (const float*)d_in[4];
    const float* vprev = (const float*)d_in[5];
    const float* W     = (const float*)d_in[6];
    const float* bb    = (const float*)d_in[7];
    const float* ln_g  = (const float*)d_in[8];
    const float* ln_b  = (const float*)d_in[9];
    float* out = (float*)d_out;

    qkv_kernel<<<BB_, 128>>>(ht, W, bb);

    dim3 g1(S1_, BB_);
    attn1_split_k<<<g1, 256>>>(kprev, vprev);

    reduce1_k<<<BB_, 128>>>(ht, W, bb, ln_g, ln_b);

    dim3 g2(S2_, BB_);
    attn2_split_k<<<g2, 256>>>(key, value, mask);

    reduce2_k<<<BB_, 128>>>(W, bb, ln_g, ln_b, out);
}

// round 2
// speedup vs baseline: 1.3429x; 1.3429x over previous
#include <cuda_runtime.h>
#include <math.h>

#define BB_ 512
#define NN_ 4096
#define DD_ 128
#define HH_ 8
#define TPREV_ 2048
#define S1_ 4
#define S2_ 8
#define CHUNK_ 512            // tokens per split CTA (2048/4 and 4096/8)
#define PSTRIDE_ 144          // 8 m + 8 l + 128 acc

// ---------------- device scratch (static; no allocations) ----------------
__device__ float g_q[BB_ * DD_];
__device__ float g_kself[BB_ * DD_];
__device__ float g_vself[BB_ * DD_];
__device__ float g_ht1[BB_ * DD_];
__device__ float g_query[BB_ * DD_];
__device__ float g_part1[BB_ * S1_ * PSTRIDE_];
__device__ float g_part2[BB_ * S2_ * PSTRIDE_];

// ---------------- helpers ----------------
__device__ __forceinline__ float warp_sum(float v) {
    v += __shfl_xor_sync(0xffffffffu, v, 16);
    v += __shfl_xor_sync(0xffffffffu, v, 8);
    v += __shfl_xor_sync(0xffffffffu, v, 4);
    v += __shfl_xor_sync(0xffffffffu, v, 2);
    v += __shfl_xor_sync(0xffffffffu, v, 1);
    return v;
}

// block of 128 threads (4 warps) sum
__device__ __forceinline__ float blk_sum128(float v, float* red, int lane, int warp) {
    v = warp_sum(v);
    __syncthreads();                 // protect red from previous use
    if (lane == 0) red[warp] = v;
    __syncthreads();
    return red[0] + red[1] + red[2] + red[3];
}

// y[r] = sum_j x[j] * Wm[r*128 + j] + bm[r]; 128 threads, warp-per-row.
__device__ __forceinline__ void gemv128(const float* __restrict__ Wm,
                                        const float* __restrict__ bm,
                                        const float* __restrict__ shx,
                                        float* __restrict__ shy,
                                        int lane, int warp) {
    float4 xv = ((const float4*)shx)[lane];
#pragma unroll 4
    for (int r = warp; r < DD_; r += 4) {
        float4 wv = __ldg(((const float4*)(Wm + r * DD_)) + lane);
        float p = fmaf(wv.x, xv.x, fmaf(wv.y, xv.y, fmaf(wv.z, xv.z, wv.w * xv.w)));
        p = warp_sum(p);
        if (lane == 0) shy[r] = p + bm[r];
    }
}

// ---------------- K0: q/k/v projections of ht ----------------
__global__ void qkv_kernel(const float* __restrict__ ht,
                           const float* __restrict__ W,
                           const float* __restrict__ bb) {
    int b = blockIdx.x;
    int tid = threadIdx.x, lane = tid & 31, warp = tid >> 5;
    __shared__ __align__(16) float shx[DD_];
    shx[tid] = ht[b * DD_ + tid];
    __syncthreads();
    float4 xv = ((const float4*)shx)[lane];
#pragma unroll
    for (int m = 0; m < 3; m++) {
        const float* Wm = W + m * DD_ * DD_;
        const float* bm = bb + m * DD_;
        float* out = (m == 0) ? g_q : ((m == 1) ? g_kself : g_vself);
#pragma unroll 4
        for (int r = warp; r < DD_; r += 4) {
            float4 wv = __ldg(((const float4*)(Wm + r * DD_)) + lane);
            float p = fmaf(wv.x, xv.x, fmaf(wv.y, xv.y, fmaf(wv.z, xv.z, wv.w * xv.w)));
            p = warp_sum(p);
            if (lane == 0) out[b * DD_ + r] = p + bm[r];
        }
    }
}

// ---------------- streaming split attention ----------------
// MASKED: tokens with mask==1 get score -1e9 in the reference; after softmax
// their weight is exp(-1e9 - M) == 0.0f exactly in fp32, so they contribute
// nothing to l or acc. We therefore skip loading K AND V for them entirely
// (warp-uniform branch: a warp owns a whole token).
template <bool MASKED>
__device__ __forceinline__ void attn_split_body(const float* __restrict__ Kv,
                                                const float* __restrict__ Vv,
                                                const int* __restrict__ mask,
                                                const float* __restrict__ qsrc,
                                                float* __restrict__ part,
                                                int T) {
    const int s = blockIdx.x, b = blockIdx.y;
    const int tid = threadIdx.x, lane = tid & 31, warp = tid >> 5;   // 8 warps

    __shared__ __align__(16) float shq[DD_];
    __shared__ int shmask[CHUNK_];
    if (tid < DD_) shq[tid] = qsrc[b * DD_ + tid];
    if (MASKED) {
        const int4* mp = (const int4*)(mask + (size_t)b * T + (size_t)s * CHUNK_);
#pragma unroll
        for (int i = tid; i < CHUNK_ / 4; i += 256)
            ((int4*)shmask)[i] = __ldcs(&mp[i]);
    }
    __syncthreads();

    const float4 qv = ((const float4*)shq)[lane];
    const size_t base4 = ((size_t)b * T + (size_t)s * CHUNK_) * (DD_ / 4);
    const float4* Kb = ((const float4*)Kv) + base4;
    const float4* Vb = ((const float4*)Vv) + base4;

    float m = -INFINITY, l = 0.f;
    float4 acc = make_float4(0.f, 0.f, 0.f, 0.f);

#pragma unroll 4
    for (int t = warp; t < CHUNK_; t += 8) {
        if (MASKED) { if (shmask[t] == 1) continue; }   // warp-uniform skip
        float4 k4 = __ldcs(&Kb[t * 32 + lane]);
        float4 v4 = __ldcs(&Vb[t * 32 + lane]);
        float dt = fmaf(k4.x, qv.x, fmaf(k4.y, qv.y, fmaf(k4.z, qv.z, k4.w * qv.w)));
        dt += __shfl_xor_sync(0xffffffffu, dt, 1);
        dt += __shfl_xor_sync(0xffffffffu, dt, 2);   // head dot (4-lane group)
        float sc = dt * 0.25f;                        // 1/sqrt(16)
        float mn = fmaxf(m, sc);
        float scale = __expf(m - mn);                 // exp(-inf)=0 on first iter
        float p = __expf(sc - mn);
        l = fmaf(l, scale, p);
        acc.x = fmaf(acc.x, scale, p * v4.x);
        acc.y = fmaf(acc.y, scale, p * v4.y);
        acc.z = fmaf(acc.z, scale, p * v4.z);
        acc.w = fmaf(acc.w, scale, p * v4.w);
        m = mn;
    }

    // cross-warp merge inside CTA
    __shared__ float sm_m[8][HH_], sm_l[8][HH_];
    __shared__ __align__(16) float sm_acc[8][DD_];
    int head = lane >> 2;
    if ((lane & 3) == 0) { sm_m[warp][head] = m; sm_l[warp][head] = l; }
    ((float4*)sm_acc[warp])[lane] = acc;
    __syncthreads();

    if (tid < DD_) {
        int h = tid >> 4;
        float M = -INFINITY;
#pragma unroll
        for (int w = 0; w < 8; w++) M = fmaxf(M, sm_m[w][h]);
        float L = 0.f, A = 0.f;
#pragma unroll
        for (int w = 0; w < 8; w++) {
            float ms = sm_m[w][h];
            float e = (ms == -INFINITY) ? 0.f : __expf(ms - M);  // avoid -inf - -inf
            L = fmaf(e, sm_l[w][h], L);
            A = fmaf(e, sm_acc[w][tid], A);
        }
        float* pp = part + ((size_t)b * gridDim.x + s) * PSTRIDE_;
        if ((tid & 15) == 0) { pp[h] = M; pp[8 + h] = L; }
        pp[16 + tid] = A;
    }
}

__global__ void __launch_bounds__(256) attn1_split_k(const float* __restrict__ Kv,
                                                     const float* __restrict__ Vv) {
    attn_split_body<false>(Kv, Vv, nullptr, g_q, g_part1, TPREV_);
}

__global__ void __launch_bounds__(256) attn2_split_k(const float* __restrict__ Kv,
                                                     const float* __restrict__ Vv,
                                                     const int* __restrict__ mask) {
    attn_split_body<true>(Kv, Vv, mask, g_query, g_part2, NN_);
}

// ---------------- K2: merge attn1 + self token, proj W3, residual, LN0, proj W4 -> query
__global__ void reduce1_k(const float* __restrict__ ht0,
                          const float* __restrict__ W,
                          const float* __restrict__ bb,
                          const float* __restrict__ lng,
                          const float* __restrict__ lnb) {
    int b = blockIdx.x, tid = threadIdx.x, lane = tid & 31, warp = tid >> 5;
    int h = tid >> 4;
    __shared__ __align__(16) float shA[DD_], shB[DD_];
    __shared__ __align__(16) float sq[DD_], sk[DD_];
    __shared__ float red[4];

    sq[tid] = g_q[b * DD_ + tid];
    sk[tid] = g_kself[b * DD_ + tid];
    __syncthreads();

    // self-token score for this thread's head
    float qk = 0.f;
#pragma unroll
    for (int j = 0; j < 16; j++) qk = fmaf(sq[h * 16 + j], sk[h * 16 + j], qk);
    float M = qk * 0.25f, L = 1.f, A = g_vself[b * DD_ + tid];

    const float* pp = g_part1 + (size_t)b * S1_ * PSTRIDE_;
#pragma unroll
    for (int s = 0; s < S1_; s++) {
        const float* p = pp + s * PSTRIDE_;
        float ms = p[h], ls = p[8 + h], as = p[16 + tid];
        float Mn = fmaxf(M, ms);
        float e0 = __expf(M - Mn);
        float e1 = (ms == -INFINITY) ? 0.f : __expf(ms - Mn);
        A = A * e0 + as * e1;
        L = L * e0 + ls * e1;
        M = Mn;
    }
    shA[tid] = A / L;
    __syncthreads();

    gemv128(W + 3 * DD_ * DD_, bb + 3 * DD_, shA, shB, lane, warp);
    __syncthreads();

    float v = ht0[b * DD_ + tid] + shB[tid];
    float mean = blk_sum128(v, red, lane, warp) * (1.f / 128.f);
    float dv = v - mean;
    float var = blk_sum128(dv * dv, red, lane, warp) * (1.f / 128.f);
    float ln = dv * rsqrtf(var + 1e-5f) * lng[tid] + lnb[tid];
    g_ht1[b * DD_ + tid] = ln;
    __syncthreads();
    shA[tid] = ln;
    __syncthreads();
    gemv128(W + 4 * DD_ * DD_, bb + 4 * DD_, shA, shB, lane, warp);
    __syncthreads();
    g_query[b * DD_ + tid] = shB[tid];
}

// ---------------- K4: merge attn2, proj W5, residual, LN1, FFN (W7 relu W6), LN2 -> out
__global__ void reduce2_k(const float* __restrict__ W,
                          const float* __restrict__ bb,
                          const float* __restrict__ lng,
                          const float* __restrict__ lnb,
                          float* __restrict__ out) {
    int b = blockIdx.x, tid = threadIdx.x, lane = tid & 31, warp = tid >> 5;
    int h = tid >> 4;
    __shared__ __align__(16) float shA[DD_], shB[DD_];
    __shared__ float red[4];

    const float* pp = g_part2 + (size_t)b * S2_ * PSTRIDE_;
    float M = -INFINITY, L = 0.f, A = 0.f;
#pragma unroll
    for (int s = 0; s < S2_; s++) {
        const float* p = pp + s * PSTRIDE_;
        float ms = p[h], ls = p[8 + h], as = p[16 + tid];
        float Mn = fmaxf(M, ms);
        float e0 = (M == -INFINITY) ? 0.f : __expf(M - Mn);
        float e1 = (ms == -INFINITY) ? 0.f : __expf(ms - Mn);
        A = A * e0 + as * e1;
        L = L * e0 + ls * e1;
        M = Mn;
    }
    shA[tid] = A / L;
    __syncthreads();

    gemv128(W + 5 * DD_ * DD_, bb + 5 * DD_, shA, shB, lane, warp);
    __syncthreads();

    float v = g_ht1[b * DD_ + tid] + shB[tid];
    float mean = blk_sum128(v, red, lane, warp) * (1.f / 128.f);
    float dv = v - mean;
    float var = blk_sum128(dv * dv, red, lane, warp) * (1.f / 128.f);
    float ht2 = dv * rsqrtf(var + 1e-5f) * lng[DD_ + tid] + lnb[DD_ + tid];
    __syncthreads();
    shA[tid] = ht2;
    __syncthreads();

    gemv128(W + 7 * DD_ * DD_, bb + 7 * DD_, shA, shB, lane, warp);   // FFN in
    __syncthreads();
    shB[tid] = fmaxf(shB[tid], 0.f);                                   // relu
    __syncthreads();
    gemv128(W + 6 * DD_ * DD_, bb + 6 * DD_, shB, shA, lane, warp);   // FFN out
    __syncthreads();

    float v2 = ht2 + shA[tid];
    float mean2 = blk_sum128(v2, red, lane, warp) * (1.f / 128.f);
    float dv2 = v2 - mean2;
    float var2 = blk_sum128(dv2 * dv2, red, lane, warp) * (1.f / 128.f);
    out[b * DD_ + tid] = dv2 * rsqrtf(var2 + 1e-5f) * lng[2 * DD_ + tid] + lnb[2 * DD_ + tid];
}

// ---------------- launch ----------------
extern "C" void kernel_launch(void* const* d_in, const int* in_sizes, int n_in,
                              void* d_out, int out_size) {
    const float* ht    = (const float*)d_in[0];
    const float* key   = (const float*)d_in[1];
    const float* value = (const float*)d_in[2];
    const int*   mask  = (const int*)  d_in[3];
    const float* kprev = (const float*)d_in[4];
    const float* vprev = (const float*)d_in[5];
    const float* W     = (const float*)d_in[6];
    const float* bb    = (const float*)d_in[7];
    const float* ln_g  = (const float*)d_in[8];
    const float* ln_b  = (const float*)d_in[9];
    float* out = (float*)d_out;

    qkv_kernel<<<BB_, 128>>>(ht, W, bb);

    dim3 g1(S1_, BB_);
    attn1_split_k<<<g1, 256>>>(kprev, vprev);

    reduce1_k<<<BB_, 128>>>(ht, W, bb, ln_g, ln_b);

    dim3 g2(S2_, BB_);
    attn2_split_k<<<g2, 256>>>(key, value, mask);

    reduce2_k<<<BB_, 128>>>(W, bb, ln_g, ln_b, out);
}

// round 3
// speedup vs baseline: 1.4154x; 1.0540x over previous
#include <cuda_runtime.h>
#include <math.h>

#define BB_ 512
#define NN_ 4096
#define DD_ 128
#define HH_ 8
#define TPREV_ 2048
#define S1_ 4
#define S2_ 8
#define CHUNK_ 512            // tokens per split CTA (2048/4 and 4096/8)
#define PSTRIDE_ 144          // 8 m + 8 l + 128 acc

// ---------------- device scratch (static; no allocations) ----------------
__device__ float g_q[BB_ * DD_];
__device__ float g_kself[BB_ * DD_];
__device__ float g_vself[BB_ * DD_];
__device__ float g_ht1[BB_ * DD_];
__device__ float g_query[BB_ * DD_];
__device__ float g_part1[BB_ * S1_ * PSTRIDE_];
__device__ float g_part2[BB_ * S2_ * PSTRIDE_];

// ---------------- helpers ----------------
__device__ __forceinline__ float warp_sum(float v) {
    v += __shfl_xor_sync(0xffffffffu, v, 16);
    v += __shfl_xor_sync(0xffffffffu, v, 8);
    v += __shfl_xor_sync(0xffffffffu, v, 4);
    v += __shfl_xor_sync(0xffffffffu, v, 2);
    v += __shfl_xor_sync(0xffffffffu, v, 1);
    return v;
}

__device__ __forceinline__ float blk_sum128(float v, float* red, int lane, int warp) {
    v = warp_sum(v);
    __syncthreads();
    if (lane == 0) red[warp] = v;
    __syncthreads();
    return red[0] + red[1] + red[2] + red[3];
}

// y[r] = sum_j x[j] * Wm[r*128 + j] + bm[r]; 128 threads, warp-per-row.
__device__ __forceinline__ void gemv128(const float* __restrict__ Wm,
                                        const float* __restrict__ bm,
                                        const float* __restrict__ shx,
                                        float* __restrict__ shy,
                                        int lane, int warp) {
    float4 xv = ((const float4*)shx)[lane];
#pragma unroll 4
    for (int r = warp; r < DD_; r += 4) {
        float4 wv = __ldg(((const float4*)(Wm + r * DD_)) + lane);
        float p = fmaf(wv.x, xv.x, fmaf(wv.y, xv.y, fmaf(wv.z, xv.z, wv.w * xv.w)));
        p = warp_sum(p);
        if (lane == 0) shy[r] = p + bm[r];
    }
}

// ---------------- K0: q/k/v projections of ht ----------------
__global__ void qkv_kernel(const float* __restrict__ ht,
                           const float* __restrict__ W,
                           const float* __restrict__ bb) {
    int b = blockIdx.x;
    int tid = threadIdx.x, lane = tid & 31, warp = tid >> 5;
    __shared__ __align__(16) float shx[DD_];
    shx[tid] = ht[b * DD_ + tid];
    __syncthreads();
    float4 xv = ((const float4*)shx)[lane];
#pragma unroll
    for (int m = 0; m < 3; m++) {
        const float* Wm = W + m * DD_ * DD_;
        const float* bm = bb + m * DD_;
        float* out = (m == 0) ? g_q : ((m == 1) ? g_kself : g_vself);
#pragma unroll 4
        for (int r = warp; r < DD_; r += 4) {
            float4 wv = __ldg(((const float4*)(Wm + r * DD_)) + lane);
            float p = fmaf(wv.x, xv.x, fmaf(wv.y, xv.y, fmaf(wv.z, xv.z, wv.w * xv.w)));
            p = warp_sum(p);
            if (lane == 0) out[b * DD_ + r] = p + bm[r];
        }
    }
}

// ---------------- core online-softmax step ----------------
__device__ __forceinline__ void osm_step(float4 k4, float4 v4, float4 qv,
                                         float& m, float& l, float4& acc) {
    float dt = fmaf(k4.x, qv.x, fmaf(k4.y, qv.y, fmaf(k4.z, qv.z, k4.w * qv.w)));
    dt += __shfl_xor_sync(0xffffffffu, dt, 1);
    dt += __shfl_xor_sync(0xffffffffu, dt, 2);     // head dot (4-lane group)
    float sc = dt * 0.25f;                          // 1/sqrt(16)
    float mn = fmaxf(m, sc);
    float scale = __expf(m - mn);                   // exp(-inf)=0 on first iter
    float p = __expf(sc - mn);
    l = fmaf(l, scale, p);
    acc.x = fmaf(acc.x, scale, p * v4.x);
    acc.y = fmaf(acc.y, scale, p * v4.y);
    acc.z = fmaf(acc.z, scale, p * v4.z);
    acc.w = fmaf(acc.w, scale, p * v4.w);
    m = mn;
}

// store CTA-merged partials
__device__ __forceinline__ void merge_and_store(float m, float l, float4 acc,
                                                float* __restrict__ part,
                                                int b, int s, int nsplit,
                                                int tid, int lane, int warp) {
    __shared__ float sm_m[8][HH_], sm_l[8][HH_];
    __shared__ __align__(16) float sm_acc[8][DD_];
    int head = lane >> 2;
    if ((lane & 3) == 0) { sm_m[warp][head] = m; sm_l[warp][head] = l; }
    ((float4*)sm_acc[warp])[lane] = acc;
    __syncthreads();

    if (tid < DD_) {
        int h = tid >> 4;
        float M = -INFINITY;
#pragma unroll
        for (int w = 0; w < 8; w++) M = fmaxf(M, sm_m[w][h]);
        float L = 0.f, A = 0.f;
#pragma unroll
        for (int w = 0; w < 8; w++) {
            float ms = sm_m[w][h];
            float e = (ms == -INFINITY) ? 0.f : __expf(ms - M);
            L = fmaf(e, sm_l[w][h], L);
            A = fmaf(e, sm_acc[w][tid], A);
        }
        float* pp = part + ((size_t)b * nsplit + s) * PSTRIDE_;
        if ((tid & 15) == 0) { pp[h] = M; pp[8 + h] = L; }
        pp[16 + tid] = A;
    }
}

// ---------------- attn1: unmasked streaming split ----------------
__global__ void __launch_bounds__(256) attn1_split_k(const float* __restrict__ Kv,
                                                     const float* __restrict__ Vv) {
    const int s = blockIdx.x, b = blockIdx.y;
    const int tid = threadIdx.x, lane = tid & 31, warp = tid >> 5;

    __shared__ __align__(16) float shq[DD_];
    if (tid < DD_) shq[tid] = g_q[b * DD_ + tid];
    __syncthreads();

    const float4 qv = ((const float4*)shq)[lane];
    const size_t base4 = ((size_t)b * TPREV_ + (size_t)s * CHUNK_) * (DD_ / 4);
    const float4* Kb = ((const float4*)Kv) + base4;
    const float4* Vb = ((const float4*)Vv) + base4;

    float m = -INFINITY, l = 0.f;
    float4 acc = make_float4(0.f, 0.f, 0.f, 0.f);

#pragma unroll 8
    for (int t = warp; t < CHUNK_; t += 8) {
        float4 k4 = __ldcs(&Kb[t * 32 + lane]);
        float4 v4 = __ldcs(&Vb[t * 32 + lane]);
        osm_step(k4, v4, qv, m, l, acc);
    }
    merge_and_store(m, l, acc, g_part1, b, s, S1_, tid, lane, warp);
}

// ---------------- attn2: masked, with deterministic compaction ----------------
// Reference gives masked tokens score -1e9; exp(-1e9 - M) == 0.0f exactly in
// fp32, so masked tokens contribute nothing. We compact the unmasked token
// indices (deterministic block prefix scan) and stream only those rows with
// UNCONDITIONAL batched loads, preserving MLP.
__global__ void __launch_bounds__(256) attn2_split_k(const float* __restrict__ Kv,
                                                     const float* __restrict__ Vv,
                                                     const int* __restrict__ mask) {
    const int s = blockIdx.x, b = blockIdx.y;
    const int tid = threadIdx.x, lane = tid & 31, warp = tid >> 5;

    __shared__ __align__(16) float shq[DD_];
    __shared__ int shidx[CHUNK_];
    __shared__ int warpsum[8];
    __shared__ int shcnt;
    if (tid < DD_) shq[tid] = g_query[b * DD_ + tid];

    // load 2 mask entries per thread
    const int2* mp = (const int2*)(mask + (size_t)b * NN_ + (size_t)s * CHUNK_);
    int2 mv = __ldcs(&mp[tid]);
    int u0 = (mv.x != 1) ? 1 : 0;
    int u1 = (mv.y != 1) ? 1 : 0;
    int cnt = u0 + u1;

    // block-wide exclusive prefix scan (deterministic)
    int pre = cnt;
#pragma unroll
    for (int d = 1; d < 32; d <<= 1) {
        int n = __shfl_up_sync(0xffffffffu, pre, d);
        if (lane >= d) pre += n;
    }
    if (lane == 31) warpsum[warp] = pre;
    __syncthreads();
    if (warp == 0) {
        int w = (lane < 8) ? warpsum[lane] : 0;
        int p = w;
#pragma unroll
        for (int d = 1; d < 8; d <<= 1) {
            int n = __shfl_up_sync(0xffffffffu, p, d);
            if (lane >= d) p += n;
        }
        if (lane < 8) warpsum[lane] = p - w;         // exclusive warp offset
        if (lane == 7) shcnt = p;                    // total unmasked
    }
    __syncthreads();
    int off = warpsum[warp] + (pre - cnt);
    if (u0) shidx[off++] = 2 * tid;
    if (u1) shidx[off] = 2 * tid + 1;
    __syncthreads();

    const int total = shcnt;
    const float4 qv = ((const float4*)shq)[lane];
    const size_t base4 = ((size_t)b * NN_ + (size_t)s * CHUNK_) * (DD_ / 4);
    const float4* Kb = ((const float4*)Kv) + base4;
    const float4* Vb = ((const float4*)Vv) + base4;

    float m = -INFINITY, l = 0.f;
    float4 acc = make_float4(0.f, 0.f, 0.f, 0.f);

#pragma unroll 4
    for (int i = warp; i < total; i += 8) {
        int t = shidx[i];
        float4 k4 = __ldcs(&Kb[t * 32 + lane]);
        float4 v4 = __ldcs(&Vb[t * 32 + lane]);
        osm_step(k4, v4, qv, m, l, acc);
    }
    merge_and_store(m, l, acc, g_part2, b, s, S2_, tid, lane, warp);
}

// ---------------- K2: merge attn1 + self token, proj W3, residual, LN0, proj W4 -> query
__global__ void reduce1_k(const float* __restrict__ ht0,
                          const float* __restrict__ W,
                          const float* __restrict__ bb,
                          const float* __restrict__ lng,
                          const float* __restrict__ lnb) {
    int b = blockIdx.x, tid = threadIdx.x, lane = tid & 31, warp = tid >> 5;
    int h = tid >> 4;
    __shared__ __align__(16) float shA[DD_], shB[DD_];
    __shared__ __align__(16) float sq[DD_], sk[DD_];
    __shared__ float red[4];

    sq[tid] = g_q[b * DD_ + tid];
    sk[tid] = g_kself[b * DD_ + tid];
    __syncthreads();

    float qk = 0.f;
#pragma unroll
    for (int j = 0; j < 16; j++) qk = fmaf(sq[h * 16 + j], sk[h * 16 + j], qk);
    float M = qk * 0.25f, L = 1.f, A = g_vself[b * DD_ + tid];

    const float* pp = g_part1 + (size_t)b * S1_ * PSTRIDE_;
#pragma unroll
    for (int s = 0; s < S1_; s++) {
        const float* p = pp + s * PSTRIDE_;
        float ms = p[h], ls = p[8 + h], as = p[16 + tid];
        float Mn = fmaxf(M, ms);
        float e0 = __expf(M - Mn);
        float e1 = (ms == -INFINITY) ? 0.f : __expf(ms - Mn);
        A = A * e0 + as * e1;
        L = L * e0 + ls * e1;
        M = Mn;
    }
    shA[tid] = A / L;
    __syncthreads();

    gemv128(W + 3 * DD_ * DD_, bb + 3 * DD_, shA, shB, lane, warp);
    __syncthreads();

    float v = ht0[b * DD_ + tid] + shB[tid];
    float mean = blk_sum128(v, red, lane, warp) * (1.f / 128.f);
    float dv = v - mean;
    float var = blk_sum128(dv * dv, red, lane, warp) * (1.f / 128.f);
    float ln = dv * rsqrtf(var + 1e-5f) * lng[tid] + lnb[tid];
    g_ht1[b * DD_ + tid] = ln;
    __syncthreads();
    shA[tid] = ln;
    __syncthreads();
    gemv128(W + 4 * DD_ * DD_, bb + 4 * DD_, shA, shB, lane, warp);
    __syncthreads();
    g_query[b * DD_ + tid] = shB[tid];
}

// ---------------- K4: merge attn2, proj W5, residual, LN1, FFN, LN2 -> out
__global__ void reduce2_k(const float* __restrict__ W,
                          const float* __restrict__ bb,
                          const float* __restrict__ lng,
                          const float* __restrict__ lnb,
                          float* __restrict__ out) {
    int b = blockIdx.x, tid = threadIdx.x, lane = tid & 31, warp = tid >> 5;
    int h = tid >> 4;
    __shared__ __align__(16) float shA[DD_], shB[DD_];
    __shared__ float red[4];

    const float* pp = g_part2 + (size_t)b * S2_ * PSTRIDE_;
    float M = -INFINITY, L = 0.f, A = 0.f;
#pragma unroll
    for (int s = 0; s < S2_; s++) {
        const float* p = pp + s * PSTRIDE_;
        float ms = p[h], ls = p[8 + h], as = p[16 + tid];
        float Mn = fmaxf(M, ms);
        float e0 = (M == -INFINITY) ? 0.f : __expf(M - Mn);
        float e1 = (ms == -INFINITY) ? 0.f : __expf(ms - Mn);
        A = A * e0 + as * e1;
        L = L * e0 + ls * e1;
        M = Mn;
    }
    shA[tid] = A / L;
    __syncthreads();

    gemv128(W + 5 * DD_ * DD_, bb + 5 * DD_, shA, shB, lane, warp);
    __syncthreads();

    float v = g_ht1[b * DD_ + tid] + shB[tid];
    float mean = blk_sum128(v, red, lane, warp) * (1.f / 128.f);
    float dv = v - mean;
    float var = blk_sum128(dv * dv, red, lane, warp) * (1.f / 128.f);
    float ht2 = dv * rsqrtf(var + 1e-5f) * lng[DD_ + tid] + lnb[DD_ + tid];
    __syncthreads();
    shA[tid] = ht2;
    __syncthreads();

    gemv128(W + 7 * DD_ * DD_, bb + 7 * DD_, shA, shB, lane, warp);   // FFN in
    __syncthreads();
    shB[tid] = fmaxf(shB[tid], 0.f);                                   // relu
    __syncthreads();
    gemv128(W + 6 * DD_ * DD_, bb + 6 * DD_, shB, shA, lane, warp);   // FFN out
    __syncthreads();

    float v2 = ht2 + shA[tid];
    float mean2 = blk_sum128(v2, red, lane, warp) * (1.f / 128.f);
    float dv2 = v2 - mean2;
    float var2 = blk_sum128(dv2 * dv2, red, lane, warp) * (1.f / 128.f);
    out[b * DD_ + tid] = dv2 * rsqrtf(var2 + 1e-5f) * lng[2 * DD_ + tid] + lnb[2 * DD_ + tid];
}

// ---------------- launch ----------------
extern "C" void kernel_launch(void* const* d_in, const int* in_sizes, int n_in,
                              void* d_out, int out_size) {
    const float* ht    = (const float*)d_in[0];
    const float* key   = (const float*)d_in[1];
    const float* value = (const float*)d_in[2];
    const int*   mask  = (const int*)  d_in[3];
    const float* kprev = (const float*)d_in[4];
    const float* vprev = (const float*)d_in[5];
    const float* W     = (const float*)d_in[6];
    const float* bb    = (const float*)d_in[7];
    const float* ln_g  = (const float*)d_in[8];
    const float* ln_b  = (const float*)d_in[9];
    float* out = (float*)d_out;

    qkv_kernel<<<BB_, 128>>>(ht, W, bb);

    dim3 g1(S1_, BB_);
    attn1_split_k<<<g1, 256>>>(kprev, vprev);

    reduce1_k<<<BB_, 128>>>(ht, W, bb, ln_g, ln_b);

    dim3 g2(S2_, BB_);
    attn2_split_k<<<g2, 256>>>(key, value, mask);

    reduce2_k<<<BB_, 128>>>(W, bb, ln_g, ln_b, out);
}